// round 9
// baseline (speedup 1.0000x reference)
#include <cuda_runtime.h>
#include <cuda_fp16.h>
#include <math.h>

#define B 64
#define N 1024
#define F_IN 64
#define E 128
#define TOPK 32
#define NEG_SLOPE 0.2f

// ---------------- scratch (device globals; no allocation allowed) ----------
__device__ __align__(16) __half g_h[B * N * E];    // 16 MB, fp16 storage
__device__ float g_es[B * N];
__device__ float g_ed[B * N];
__device__ __align__(16) float g_embn[N * E];      // normalized emb
__device__ float g_eemb_s[N];
__device__ float g_eemb_d[N];
__device__ __align__(16) float g_ws[2 * F_IN];     // [ws_src | ws_dst]
__device__ int   g_idx[N * TOPK];
__device__ __align__(16) float g_sims[N * N];      // 4 MB cosine sims
#define WT_STRIDE 72
__device__ __align__(16) __half g_wt[E * WT_STRIDE];  // W^T fp16, padded rows

// ---------------- K0: ws_src[f] = sum_e W_fe[f,e]*a_src[e]  (and dst) ------
__global__ void k0_ws(const float* __restrict__ Wfe,
                      const float* __restrict__ a_src,
                      const float* __restrict__ a_dst) {
    int t = threadIdx.x;  // 128 threads
    if (t < F_IN) {
        float s = 0.f;
        #pragma unroll 8
        for (int e = 0; e < E; e++) s += Wfe[t * E + e] * a_src[e];
        g_ws[t] = s;
    } else {
        int f = t - F_IN;
        float s = 0.f;
        #pragma unroll 8
        for (int e = 0; e < E; e++) s += Wfe[f * E + e] * a_dst[e];
        g_ws[F_IN + f] = s;
    }
}

// ---------------- K_wt: W^T fp16, padded [E][72] --------------------------
__global__ void k_wt(const float* __restrict__ Wfe) {
    int idx = blockIdx.x * 256 + threadIdx.x;   // 0..8191 = e*64+f
    int e = idx >> 6, f = idx & 63;
    g_wt[e * WT_STRIDE + f] = __float2half_rn(Wfe[f * E + e]);
}

// ---------------- K1a: normalize emb rows + emb-side attention dots --------
__global__ void k1a_norm(const float* __restrict__ emb,
                         const float* __restrict__ a_src,
                         const float* __restrict__ a_dst) {
    int n = blockIdx.x;
    int e = threadIdx.x;  // 128
    int lane = e & 31, wid = e >> 5;
    __shared__ float sm[12];
    float v  = emb[n * E + e];
    float r0 = v * v;
    float r1 = v * a_src[E + e];
    float r2 = v * a_dst[E + e];
    #pragma unroll
    for (int o = 16; o; o >>= 1) {
        r0 += __shfl_xor_sync(0xffffffffu, r0, o);
        r1 += __shfl_xor_sync(0xffffffffu, r1, o);
        r2 += __shfl_xor_sync(0xffffffffu, r2, o);
    }
    if (lane == 0) { sm[wid] = r0; sm[4 + wid] = r1; sm[8 + wid] = r2; }
    __syncthreads();
    float sumsq = sm[0] + sm[1] + sm[2] + sm[3];
    g_embn[n * E + e] = v * rsqrtf(sumsq);
    if (e == 0) {
        g_eemb_s[n] = sm[4] + sm[5] + sm[6] + sm[7];
        g_eemb_d[n] = sm[8] + sm[9] + sm[10] + sm[11];
    }
}

// ---------------- K1b-sim: sims tile 8 rows x 256 cols per block -----------
#define SR 8
#define SC 256
__global__ void __launch_bounds__(256) k1b_sim() {
    __shared__ __align__(16) float q[SR * E];   // 4 KB
    int tid = threadIdx.x;                       // 256
    int row0 = blockIdx.x * SR;                  // blockIdx.x in [0,128)
    int col0 = blockIdx.y * SC;                  // blockIdx.y in [0,4)

    #pragma unroll
    for (int i = 0; i < 4; i++) q[tid + i * 256] = g_embn[row0 * E + tid + i * 256];
    __syncthreads();

    const float4* q4 = (const float4*)q;
    int c = col0 + tid;
    float acc[SR];
    #pragma unroll
    for (int r = 0; r < SR; r++) acc[r] = 0.f;
    const float4* rp = (const float4*)g_embn + (size_t)c * (E / 4);
    #pragma unroll 8
    for (int j = 0; j < E / 4; j++) {
        float4 rv = rp[j];
        #pragma unroll
        for (int r = 0; r < SR; r++) {
            float4 qv = q4[r * (E / 4) + j];
            acc[r] += rv.x * qv.x + rv.y * qv.y + rv.z * qv.z + rv.w * qv.w;
        }
    }
    #pragma unroll
    for (int r = 0; r < SR; r++) g_sims[(size_t)(row0 + r) * N + c] = acc[r];
}

// ---------------- K1b-sel: warp per row, top-32 (set semantics) ------------
__global__ void __launch_bounds__(256) k1b_sel() {
    int tid = threadIdx.x;
    int wid = tid >> 5, lane = tid & 31;
    int r = blockIdx.x * 8 + wid;                // row in [0,1024)

    const float* srow = g_sims + (size_t)r * N;
    float vals[32];
    #pragma unroll
    for (int j = 0; j < 32; j++) vals[j] = srow[j * 32 + lane];  // coalesced

    float bv = vals[0]; int bj = 0;
    #pragma unroll
    for (int j = 1; j < 32; j++)
        if (vals[j] > bv) { bv = vals[j]; bj = j; }

    for (int round = 0; round < TOPK; round++) {
        float wv = bv;
        int   wi = bj * 32 + lane;   // global column
        #pragma unroll
        for (int o = 16; o; o >>= 1) {
            float ov = __shfl_xor_sync(0xffffffffu, wv, o);
            int   oi = __shfl_xor_sync(0xffffffffu, wi, o);
            if (ov > wv || (ov == wv && oi < wi)) { wv = ov; wi = oi; }
        }
        if (lane == 0) g_idx[r * TOPK + round] = wi;
        if (lane == (wi & 31)) {
            int jw = wi >> 5;
            #pragma unroll
            for (int j = 0; j < 32; j++) if (j == jw) vals[j] = -INFINITY;
            bv = vals[0]; bj = 0;
            #pragma unroll
            for (int j = 1; j < 32; j++)
                if (vals[j] > bv) { bv = vals[j]; bj = j; }
        }
        __syncwarp();
    }
}

// ---------------- K2: h = x @ W_fe via tensor cores; fused e_s/e_d ---------
// block: 256 thr = 8 warps (4 m x 2 n); tile 64 tokens x 128 E; K = 64.
#define TOK 64
#define XS_STRIDE 72      // halves, padded
#define CS_STRIDE 136     // halves, padded

__device__ __forceinline__ void mma16816(float* c, const unsigned* a, const unsigned* b) {
    asm volatile(
        "mma.sync.aligned.m16n8k16.row.col.f32.f16.f16.f32 "
        "{%0,%1,%2,%3}, {%4,%5,%6,%7}, {%8,%9}, {%0,%1,%2,%3};\n"
        : "+f"(c[0]), "+f"(c[1]), "+f"(c[2]), "+f"(c[3])
        : "r"(a[0]), "r"(a[1]), "r"(a[2]), "r"(a[3]), "r"(b[0]), "r"(b[1]));
}

__global__ void __launch_bounds__(256) k2_tc(const float* __restrict__ x) {
    // xs: [64][72] halves (9216B), Ws: [128][72] halves (18432B)
    __shared__ __align__(16) char sbuf[TOK * XS_STRIDE * 2 + E * WT_STRIDE * 2];
    __half* xs = (__half*)sbuf;
    __half* Ws = (__half*)(sbuf + TOK * XS_STRIDE * 2);
    int tid = threadIdx.x;
    int t0 = blockIdx.x * TOK;

    {
        // W^T copy: straight uint4 copy of pre-padded fp16 data (1152 uint4)
        const uint4* wsrc = (const uint4*)g_wt;
        uint4* wdst = (uint4*)Ws;
        #pragma unroll
        for (int i = 0; i < 5; i++) {
            int idx = tid + i * 256;
            if (idx < (E * WT_STRIDE * 2) / 16) wdst[idx] = wsrc[idx];
        }
        // x tile load + fp16 convert + fused e_s/e_d
        const float4* xsrc = (const float4*)(x + (size_t)t0 * F_IN);
        const float4* ws4  = (const float4*)g_ws;
        int c4 = tid & 15;
        float4 wsv = __ldg(ws4 + c4);        // ws_src[f4]
        float4 wdv = __ldg(ws4 + 16 + c4);   // ws_dst[f4]
        #pragma unroll
        for (int it = 0; it < 4; it++) {
            int idx = tid + it * 256;     // 0..1023 float4
            int row = idx >> 4;
            float4 v = xsrc[idx];
            __half2* dst = (__half2*)(xs + row * XS_STRIDE + c4 * 4);
            dst[0] = __floats2half2_rn(v.x, v.y);
            dst[1] = __floats2half2_rn(v.z, v.w);
            float s = v.x * wsv.x + v.y * wsv.y + v.z * wsv.z + v.w * wsv.w;
            float d = v.x * wdv.x + v.y * wdv.y + v.z * wdv.z + v.w * wdv.w;
            #pragma unroll
            for (int o = 8; o; o >>= 1) {
                s += __shfl_xor_sync(0xffffffffu, s, o);
                d += __shfl_xor_sync(0xffffffffu, d, o);
            }
            if (c4 == 0) {
                int gt = t0 + row;
                int n = gt & (N - 1);
                g_es[gt] = s + __ldg(&g_eemb_s[n]);
                g_ed[gt] = d + __ldg(&g_eemb_d[n]);
            }
        }
    }
    __syncthreads();

    int lane = tid & 31, warp = tid >> 5;
    int wm = warp & 3, wn = warp >> 2;       // m off = wm*16, n off = wn*64
    int gid = lane >> 2, qid = lane & 3;

    float c[8][4];
    #pragma unroll
    for (int ni = 0; ni < 8; ni++)
        #pragma unroll
        for (int q = 0; q < 4; q++) c[ni][q] = 0.f;

    #pragma unroll
    for (int kk = 0; kk < F_IN; kk += 16) {
        unsigned a[4];
        {
            int r = wm * 16 + gid;
            int cb = qid * 2 + kk;
            a[0] = *(unsigned*)(xs + r * XS_STRIDE + cb);
            a[1] = *(unsigned*)(xs + (r + 8) * XS_STRIDE + cb);
            a[2] = *(unsigned*)(xs + r * XS_STRIDE + cb + 8);
            a[3] = *(unsigned*)(xs + (r + 8) * XS_STRIDE + cb + 8);
        }
        #pragma unroll
        for (int ni = 0; ni < 8; ni++) {
            int col = wn * 64 + ni * 8 + gid;
            int rb = qid * 2 + kk;
            unsigned bb[2];
            bb[0] = *(unsigned*)(Ws + col * WT_STRIDE + rb);
            bb[1] = *(unsigned*)(Ws + col * WT_STRIDE + rb + 8);
            mma16816(c[ni], a, bb);
        }
    }
    __syncthreads();  // done reading xs/Ws

    // stage C tile in smem fp16 for coalesced global store
    __half* cs = (__half*)sbuf;   // [64][136] = 17408 B
    #pragma unroll
    for (int ni = 0; ni < 8; ni++) {
        int r = wm * 16 + gid;
        int e = wn * 64 + ni * 8 + qid * 2;
        *(__half2*)(cs + r * CS_STRIDE + e) =
            __floats2half2_rn(c[ni][0], c[ni][1]);
        *(__half2*)(cs + (r + 8) * CS_STRIDE + e) =
            __floats2half2_rn(c[ni][2], c[ni][3]);
    }
    __syncthreads();

    uint4* dst = (uint4*)(g_h + (size_t)t0 * E);
    #pragma unroll
    for (int it = 0; it < 4; it++) {
        int idx = tid + it * 256;   // 0..1023 uint4; 16 per row
        int row = idx >> 4;
        int c8  = idx & 15;
        dst[idx] = *(uint4*)(cs + row * CS_STRIDE + c8 * 8);
    }
}

// ---------------- K3: attention softmax + gather-weighted sum + head -------
// 256 thr = 8 warps, 1 token per warp; half-warp covers one row (LDG.128).
__global__ void __launch_bounds__(256) k3_out(const float* __restrict__ lin_W,
                                              const float* __restrict__ lin_b,
                                              float* __restrict__ y) {
    int tid = threadIdx.x;
    int wid = tid >> 5, lane = tid & 31;
    int t = blockIdx.x * 8 + wid;
    int b = t >> 10;
    int n = t & (N - 1);

    int   i  = g_idx[n * TOPK + lane];      // lane = k
    float ed = g_ed[(b << 10) + i];
    float es = g_es[t];
    float sc = es + ed;
    sc = sc >= 0.f ? sc : NEG_SLOPE * sc;

    float m = sc;
    #pragma unroll
    for (int o = 16; o; o >>= 1) m = fmaxf(m, __shfl_xor_sync(0xffffffffu, m, o));
    float p = __expf(sc - m);
    float s = p;
    #pragma unroll
    for (int o = 16; o; o >>= 1) s += __shfl_xor_sync(0xffffffffu, s, o);
    float alpha = p / s;

    const __half* hb = g_h + ((size_t)b << 10) * E;
    int hw = lane >> 4, sl = lane & 15;     // half-warp id, slice (e = sl*8..+8)

    // gather all (alpha, idx) for this half-warp's 16 k's up front
    float aw[16]; int idxs[16];
    #pragma unroll
    for (int j = 0; j < 16; j++) {
        int kk = j * 2 + hw;
        aw[j]   = __shfl_sync(0xffffffffu, alpha, kk);
        idxs[j] = __shfl_sync(0xffffffffu, i, kk);
    }

    float acc[8];
    #pragma unroll
    for (int q = 0; q < 8; q++) acc[q] = 0.f;

    // two batches of 8 loads -> MLP=8 in flight
    #pragma unroll
    for (int half = 0; half < 2; half++) {
        uint4 raw[8];
        #pragma unroll
        for (int j = 0; j < 8; j++)
            raw[j] = *(const uint4*)(hb + (size_t)idxs[half * 8 + j] * E + sl * 8);
        #pragma unroll
        for (int j = 0; j < 8; j++) {
            float a = aw[half * 8 + j];
            __half2* hp = (__half2*)&raw[j];
            #pragma unroll
            for (int q = 0; q < 4; q++) {
                float2 f = __half22float2(hp[q]);
                acc[q * 2]     += a * f.x;
                acc[q * 2 + 1] += a * f.y;
            }
        }
    }
    // combine even-k / odd-k halves
    #pragma unroll
    for (int q = 0; q < 8; q++) acc[q] += __shfl_xor_sync(0xffffffffu, acc[q], 16);

    const float4* lw4 = (const float4*)lin_W;
    float4 l0 = lw4[sl * 2], l1 = lw4[sl * 2 + 1];
    float part = fmaxf(acc[0], 0.f) * l0.x + fmaxf(acc[1], 0.f) * l0.y
               + fmaxf(acc[2], 0.f) * l0.z + fmaxf(acc[3], 0.f) * l0.w
               + fmaxf(acc[4], 0.f) * l1.x + fmaxf(acc[5], 0.f) * l1.y
               + fmaxf(acc[6], 0.f) * l1.z + fmaxf(acc[7], 0.f) * l1.w;
    #pragma unroll
    for (int o = 8; o; o >>= 1) part += __shfl_xor_sync(0xffffffffu, part, o);
    if (lane == 0) y[t] = part + lin_b[0];
}

// ---------------- launch (fork k1b path onto side stream, overlap k2) ------
extern "C" void kernel_launch(void* const* d_in, const int* in_sizes, int n_in,
                              void* d_out, int out_size) {
    const float* x     = (const float*)d_in[0];
    const float* emb   = (const float*)d_in[1];
    const float* Wfe   = (const float*)d_in[2];
    const float* a_src = (const float*)d_in[3];
    const float* a_dst = (const float*)d_in[4];
    const float* lin_W = (const float*)d_in[5];
    const float* lin_b = (const float*)d_in[6];
    float* y = (float*)d_out;

    static cudaStream_t s2 = nullptr;
    static cudaEvent_t evFork = nullptr, evJoin = nullptr;
    if (s2 == nullptr) {
        cudaStreamCreateWithFlags(&s2, cudaStreamNonBlocking);
        cudaEventCreateWithFlags(&evFork, cudaEventDisableTiming);
        cudaEventCreateWithFlags(&evJoin, cudaEventDisableTiming);
    }

    k0_ws<<<1, 128>>>(Wfe, a_src, a_dst);
    k_wt<<<(E * F_IN) / 256, 256>>>(Wfe);
    k1a_norm<<<N, 128>>>(emb, a_src, a_dst);
    cudaEventRecord(evFork, 0);
    cudaStreamWaitEvent(s2, evFork, 0);
    {   // emb path on side stream
        dim3 gsim(N / SR, N / SC);
        k1b_sim<<<gsim, 256, 0, s2>>>();
        k1b_sel<<<N / 8, 256, 0, s2>>>();
    }
    cudaEventRecord(evJoin, s2);
    k2_tc<<<(B * N) / TOK, 256>>>(x);              // x path on main stream
    cudaStreamWaitEvent(0, evJoin, 0);
    k3_out<<<(B * N) / 8, 256>>>(lin_W, lin_b, y);
}

// round 10
// speedup vs baseline: 1.5490x; 1.5490x over previous
#include <cuda_runtime.h>
#include <cuda_fp16.h>
#include <math.h>

#define B 64
#define N 1024
#define F_IN 64
#define E 128
#define TOPK 32
#define NEG_SLOPE 0.2f

// ---------------- scratch (device globals; no allocation allowed) ----------
__device__ __align__(16) __half g_h[B * N * E];    // 16 MB, fp16 storage
__device__ float g_es[B * N];
__device__ float g_ed[B * N];
__device__ __align__(16) float g_embn[N * E];      // normalized emb
__device__ float g_eemb_s[N];
__device__ float g_eemb_d[N];
__device__ __align__(16) float g_ws[2 * F_IN];     // [ws_src | ws_dst]
__device__ int   g_idx[N * TOPK];
__device__ __align__(16) float g_sims[N * N];      // 4 MB cosine sims
#define WT_STRIDE 72
__device__ __align__(16) __half g_wt[E * WT_STRIDE];  // W^T fp16, padded rows

// ---------------- K0: ws_src[f] = sum_e W_fe[f,e]*a_src[e]  (and dst) ------
__global__ void k0_ws(const float* __restrict__ Wfe,
                      const float* __restrict__ a_src,
                      const float* __restrict__ a_dst) {
    int t = threadIdx.x;  // 128 threads
    if (t < F_IN) {
        float s = 0.f;
        #pragma unroll 8
        for (int e = 0; e < E; e++) s += Wfe[t * E + e] * a_src[e];
        g_ws[t] = s;
    } else {
        int f = t - F_IN;
        float s = 0.f;
        #pragma unroll 8
        for (int e = 0; e < E; e++) s += Wfe[f * E + e] * a_dst[e];
        g_ws[F_IN + f] = s;
    }
}

// ---------------- K_wt: W^T fp16, padded [E][72] --------------------------
__global__ void k_wt(const float* __restrict__ Wfe) {
    int idx = blockIdx.x * 256 + threadIdx.x;   // 0..8191 = e*64+f
    int e = idx >> 6, f = idx & 63;
    g_wt[e * WT_STRIDE + f] = __float2half_rn(Wfe[f * E + e]);
}

// ---------------- K1a: normalize emb rows + emb-side attention dots --------
__global__ void k1a_norm(const float* __restrict__ emb,
                         const float* __restrict__ a_src,
                         const float* __restrict__ a_dst) {
    int n = blockIdx.x;
    int e = threadIdx.x;  // 128
    int lane = e & 31, wid = e >> 5;
    __shared__ float sm[12];
    float v  = emb[n * E + e];
    float r0 = v * v;
    float r1 = v * a_src[E + e];
    float r2 = v * a_dst[E + e];
    #pragma unroll
    for (int o = 16; o; o >>= 1) {
        r0 += __shfl_xor_sync(0xffffffffu, r0, o);
        r1 += __shfl_xor_sync(0xffffffffu, r1, o);
        r2 += __shfl_xor_sync(0xffffffffu, r2, o);
    }
    if (lane == 0) { sm[wid] = r0; sm[4 + wid] = r1; sm[8 + wid] = r2; }
    __syncthreads();
    float sumsq = sm[0] + sm[1] + sm[2] + sm[3];
    g_embn[n * E + e] = v * rsqrtf(sumsq);
    if (e == 0) {
        g_eemb_s[n] = sm[4] + sm[5] + sm[6] + sm[7];
        g_eemb_d[n] = sm[8] + sm[9] + sm[10] + sm[11];
    }
}

// ---------------- K1b-sim: tiled GEMM  sims = embn @ embn^T ---------------
// block 256 thr = 16x16; C tile 64x64; K chunks of 32; coalesced smem loads.
#define KC 32
#define AS_STRIDE 33
__global__ void __launch_bounds__(256) k1b_sim() {
    __shared__ float As[64 * AS_STRIDE];   // rows tile  (8.4 KB)
    __shared__ float Bs[64 * AS_STRIDE];   // cols tile  (8.4 KB)
    int tid = threadIdx.x;
    int r0 = blockIdx.y * 64;
    int c0 = blockIdx.x * 64;
    int lrow = tid >> 5, lcol = tid & 31;   // load: warp = one 128B row chunk
    int ty = tid >> 4, tx = tid & 15;       // compute: 4x4 per thread

    float acc[4][4];
    #pragma unroll
    for (int i = 0; i < 4; i++)
        #pragma unroll
        for (int j = 0; j < 4; j++) acc[i][j] = 0.f;

    for (int kk = 0; kk < E; kk += KC) {
        // load 64 rows x 32 cols, coalesced (8 rows per iter)
        #pragma unroll
        for (int it = 0; it < 8; it++) {
            int row = lrow + it * 8;
            As[row * AS_STRIDE + lcol] = g_embn[(size_t)(r0 + row) * E + kk + lcol];
            Bs[row * AS_STRIDE + lcol] = g_embn[(size_t)(c0 + row) * E + kk + lcol];
        }
        __syncthreads();

        #pragma unroll
        for (int k = 0; k < KC; k++) {
            float a[4], b[4];
            #pragma unroll
            for (int i = 0; i < 4; i++) a[i] = As[(ty * 4 + i) * AS_STRIDE + k];
            #pragma unroll
            for (int j = 0; j < 4; j++) b[j] = Bs[(tx * 4 + j) * AS_STRIDE + k];
            #pragma unroll
            for (int i = 0; i < 4; i++)
                #pragma unroll
                for (int j = 0; j < 4; j++) acc[i][j] += a[i] * b[j];
        }
        __syncthreads();
    }

    #pragma unroll
    for (int i = 0; i < 4; i++) {
        #pragma unroll
        for (int j = 0; j < 4; j++)
            g_sims[(size_t)(r0 + ty * 4 + i) * N + c0 + tx * 4 + j] = acc[i][j];
    }
}

// ---------------- K1b-sel: warp per row, top-32 (set semantics) ------------
__global__ void __launch_bounds__(256) k1b_sel() {
    int tid = threadIdx.x;
    int wid = tid >> 5, lane = tid & 31;
    int r = blockIdx.x * 8 + wid;                // row in [0,1024)

    const float* srow = g_sims + (size_t)r * N;
    float vals[32];
    #pragma unroll
    for (int j = 0; j < 32; j++) vals[j] = srow[j * 32 + lane];  // coalesced

    float bv = vals[0]; int bj = 0;
    #pragma unroll
    for (int j = 1; j < 32; j++)
        if (vals[j] > bv) { bv = vals[j]; bj = j; }

    for (int round = 0; round < TOPK; round++) {
        float wv = bv;
        int   wi = bj * 32 + lane;   // global column
        #pragma unroll
        for (int o = 16; o; o >>= 1) {
            float ov = __shfl_xor_sync(0xffffffffu, wv, o);
            int   oi = __shfl_xor_sync(0xffffffffu, wi, o);
            if (ov > wv || (ov == wv && oi < wi)) { wv = ov; wi = oi; }
        }
        if (lane == 0) g_idx[r * TOPK + round] = wi;
        if (lane == (wi & 31)) {
            int jw = wi >> 5;
            #pragma unroll
            for (int j = 0; j < 32; j++) if (j == jw) vals[j] = -INFINITY;
            bv = vals[0]; bj = 0;
            #pragma unroll
            for (int j = 1; j < 32; j++)
                if (vals[j] > bv) { bv = vals[j]; bj = j; }
        }
        __syncwarp();
    }
}

// ---------------- K2: h = x @ W_fe via tensor cores; fused e_s/e_d ---------
// block: 256 thr = 8 warps (4 m x 2 n); tile 64 tokens x 128 E; K = 64.
#define TOK 64
#define XS_STRIDE 72      // halves, padded
#define CS_STRIDE 136     // halves, padded

__device__ __forceinline__ void mma16816(float* c, const unsigned* a, const unsigned* b) {
    asm volatile(
        "mma.sync.aligned.m16n8k16.row.col.f32.f16.f16.f32 "
        "{%0,%1,%2,%3}, {%4,%5,%6,%7}, {%8,%9}, {%0,%1,%2,%3};\n"
        : "+f"(c[0]), "+f"(c[1]), "+f"(c[2]), "+f"(c[3])
        : "r"(a[0]), "r"(a[1]), "r"(a[2]), "r"(a[3]), "r"(b[0]), "r"(b[1]));
}

__global__ void __launch_bounds__(256) k2_tc(const float* __restrict__ x) {
    // xs: [64][72] halves (9216B), Ws: [128][72] halves (18432B)
    __shared__ __align__(16) char sbuf[TOK * XS_STRIDE * 2 + E * WT_STRIDE * 2];
    __half* xs = (__half*)sbuf;
    __half* Ws = (__half*)(sbuf + TOK * XS_STRIDE * 2);
    int tid = threadIdx.x;
    int t0 = blockIdx.x * TOK;

    {
        // W^T copy: straight uint4 copy of pre-padded fp16 data (1152 uint4)
        const uint4* wsrc = (const uint4*)g_wt;
        uint4* wdst = (uint4*)Ws;
        #pragma unroll
        for (int i = 0; i < 5; i++) {
            int idx = tid + i * 256;
            if (idx < (E * WT_STRIDE * 2) / 16) wdst[idx] = wsrc[idx];
        }
        // x tile load + fp16 convert + fused e_s/e_d
        const float4* xsrc = (const float4*)(x + (size_t)t0 * F_IN);
        const float4* ws4  = (const float4*)g_ws;
        int c4 = tid & 15;
        float4 wsv = __ldg(ws4 + c4);        // ws_src[f4]
        float4 wdv = __ldg(ws4 + 16 + c4);   // ws_dst[f4]
        #pragma unroll
        for (int it = 0; it < 4; it++) {
            int idx = tid + it * 256;     // 0..1023 float4
            int row = idx >> 4;
            float4 v = xsrc[idx];
            __half2* dst = (__half2*)(xs + row * XS_STRIDE + c4 * 4);
            dst[0] = __floats2half2_rn(v.x, v.y);
            dst[1] = __floats2half2_rn(v.z, v.w);
            float s = v.x * wsv.x + v.y * wsv.y + v.z * wsv.z + v.w * wsv.w;
            float d = v.x * wdv.x + v.y * wdv.y + v.z * wdv.z + v.w * wdv.w;
            #pragma unroll
            for (int o = 8; o; o >>= 1) {
                s += __shfl_xor_sync(0xffffffffu, s, o);
                d += __shfl_xor_sync(0xffffffffu, d, o);
            }
            if (c4 == 0) {
                int gt = t0 + row;
                int n = gt & (N - 1);
                g_es[gt] = s + __ldg(&g_eemb_s[n]);
                g_ed[gt] = d + __ldg(&g_eemb_d[n]);
            }
        }
    }
    __syncthreads();

    int lane = tid & 31, warp = tid >> 5;
    int wm = warp & 3, wn = warp >> 2;       // m off = wm*16, n off = wn*64
    int gid = lane >> 2, qid = lane & 3;

    float c[8][4];
    #pragma unroll
    for (int ni = 0; ni < 8; ni++)
        #pragma unroll
        for (int q = 0; q < 4; q++) c[ni][q] = 0.f;

    #pragma unroll
    for (int kk = 0; kk < F_IN; kk += 16) {
        unsigned a[4];
        {
            int r = wm * 16 + gid;
            int cb = qid * 2 + kk;
            a[0] = *(unsigned*)(xs + r * XS_STRIDE + cb);
            a[1] = *(unsigned*)(xs + (r + 8) * XS_STRIDE + cb);
            a[2] = *(unsigned*)(xs + r * XS_STRIDE + cb + 8);
            a[3] = *(unsigned*)(xs + (r + 8) * XS_STRIDE + cb + 8);
        }
        #pragma unroll
        for (int ni = 0; ni < 8; ni++) {
            int col = wn * 64 + ni * 8 + gid;
            int rb = qid * 2 + kk;
            unsigned bb[2];
            bb[0] = *(unsigned*)(Ws + col * WT_STRIDE + rb);
            bb[1] = *(unsigned*)(Ws + col * WT_STRIDE + rb + 8);
            mma16816(c[ni], a, bb);
        }
    }
    __syncthreads();  // done reading xs/Ws

    // stage C tile in smem fp16 for coalesced global store
    __half* cs = (__half*)sbuf;   // [64][136] = 17408 B
    #pragma unroll
    for (int ni = 0; ni < 8; ni++) {
        int r = wm * 16 + gid;
        int e = wn * 64 + ni * 8 + qid * 2;
        *(__half2*)(cs + r * CS_STRIDE + e) =
            __floats2half2_rn(c[ni][0], c[ni][1]);
        *(__half2*)(cs + (r + 8) * CS_STRIDE + e) =
            __floats2half2_rn(c[ni][2], c[ni][3]);
    }
    __syncthreads();

    uint4* dst = (uint4*)(g_h + (size_t)t0 * E);
    #pragma unroll
    for (int it = 0; it < 4; it++) {
        int idx = tid + it * 256;   // 0..1023 uint4; 16 per row
        int row = idx >> 4;
        int c8  = idx & 15;
        dst[idx] = *(uint4*)(cs + row * CS_STRIDE + c8 * 8);
    }
}

// ---------------- K3: attention softmax + gather-weighted sum + head -------
// 256 thr = 8 warps, 1 token per warp; half-warp covers one row (LDG.128).
__global__ void __launch_bounds__(256) k3_out(const float* __restrict__ lin_W,
                                              const float* __restrict__ lin_b,
                                              float* __restrict__ y) {
    int tid = threadIdx.x;
    int wid = tid >> 5, lane = tid & 31;
    int t = blockIdx.x * 8 + wid;
    int b = t >> 10;
    int n = t & (N - 1);

    int   i  = g_idx[n * TOPK + lane];      // lane = k
    float ed = g_ed[(b << 10) + i];
    float es = g_es[t];
    float sc = es + ed;
    sc = sc >= 0.f ? sc : NEG_SLOPE * sc;

    float m = sc;
    #pragma unroll
    for (int o = 16; o; o >>= 1) m = fmaxf(m, __shfl_xor_sync(0xffffffffu, m, o));
    float p = __expf(sc - m);
    float s = p;
    #pragma unroll
    for (int o = 16; o; o >>= 1) s += __shfl_xor_sync(0xffffffffu, s, o);
    float alpha = p / s;

    const __half* hb = g_h + ((size_t)b << 10) * E;
    int hw = lane >> 4, sl = lane & 15;     // half-warp id, slice (e = sl*8..+8)

    // gather all (alpha, idx) for this half-warp's 16 k's up front
    float aw[16]; int idxs[16];
    #pragma unroll
    for (int j = 0; j < 16; j++) {
        int kk = j * 2 + hw;
        aw[j]   = __shfl_sync(0xffffffffu, alpha, kk);
        idxs[j] = __shfl_sync(0xffffffffu, i, kk);
    }

    float acc[8];
    #pragma unroll
    for (int q = 0; q < 8; q++) acc[q] = 0.f;

    // two batches of 8 loads -> MLP=8 in flight
    #pragma unroll
    for (int half = 0; half < 2; half++) {
        uint4 raw[8];
        #pragma unroll
        for (int j = 0; j < 8; j++)
            raw[j] = *(const uint4*)(hb + (size_t)idxs[half * 8 + j] * E + sl * 8);
        #pragma unroll
        for (int j = 0; j < 8; j++) {
            float a = aw[half * 8 + j];
            __half2* hp = (__half2*)&raw[j];
            #pragma unroll
            for (int q = 0; q < 4; q++) {
                float2 f = __half22float2(hp[q]);
                acc[q * 2]     += a * f.x;
                acc[q * 2 + 1] += a * f.y;
            }
        }
    }
    // combine even-k / odd-k halves
    #pragma unroll
    for (int q = 0; q < 8; q++) acc[q] += __shfl_xor_sync(0xffffffffu, acc[q], 16);

    const float4* lw4 = (const float4*)lin_W;
    float4 l0 = lw4[sl * 2], l1 = lw4[sl * 2 + 1];
    float part = fmaxf(acc[0], 0.f) * l0.x + fmaxf(acc[1], 0.f) * l0.y
               + fmaxf(acc[2], 0.f) * l0.z + fmaxf(acc[3], 0.f) * l0.w
               + fmaxf(acc[4], 0.f) * l1.x + fmaxf(acc[5], 0.f) * l1.y
               + fmaxf(acc[6], 0.f) * l1.z + fmaxf(acc[7], 0.f) * l1.w;
    #pragma unroll
    for (int o = 8; o; o >>= 1) part += __shfl_xor_sync(0xffffffffu, part, o);
    if (lane == 0) y[t] = part + lin_b[0];
}

// ---------------- launch (single stream, fully serial) ---------------------
extern "C" void kernel_launch(void* const* d_in, const int* in_sizes, int n_in,
                              void* d_out, int out_size) {
    const float* x     = (const float*)d_in[0];
    const float* emb   = (const float*)d_in[1];
    const float* Wfe   = (const float*)d_in[2];
    const float* a_src = (const float*)d_in[3];
    const float* a_dst = (const float*)d_in[4];
    const float* lin_W = (const float*)d_in[5];
    const float* lin_b = (const float*)d_in[6];
    float* y = (float*)d_out;

    k0_ws<<<1, 128>>>(Wfe, a_src, a_dst);
    k_wt<<<(E * F_IN) / 256, 256>>>(Wfe);
    k1a_norm<<<N, 128>>>(emb, a_src, a_dst);
    {
        dim3 gsim(N / 64, N / 64);
        k1b_sim<<<gsim, 256>>>();
    }
    k1b_sel<<<N / 8, 256>>>();
    k2_tc<<<(B * N) / TOK, 256>>>(x);
    k3_out<<<(B * N) / 8, 256>>>(lin_W, lin_b, y);
}

// round 11
// speedup vs baseline: 1.6518x; 1.0664x over previous
#include <cuda_runtime.h>
#include <cuda_fp16.h>
#include <math.h>

#define B 64
#define N 1024
#define F_IN 64
#define E 128
#define TOPK 32
#define NEG_SLOPE 0.2f

// ---------------- scratch (device globals; no allocation allowed) ----------
__device__ __align__(16) __half g_h[B * N * E];    // 16 MB, fp16 storage
__device__ float g_es[B * N];
__device__ float g_ed[B * N];
__device__ __align__(16) float g_embn[N * E];      // normalized emb
__device__ float g_eemb_s[N];
__device__ float g_eemb_d[N];
__device__ __align__(16) float g_ws[2 * F_IN];     // [ws_src | ws_dst]
__device__ int   g_idx[N * TOPK];
__device__ __align__(16) float g_sims[N * N];      // 4 MB cosine sims
__device__ float g_part[2 * B * N];                // per-e-half partial dots
#define WT_STRIDE 72
__device__ __align__(16) __half g_wt[E * WT_STRIDE];  // W^T fp16, padded rows

// ---------------- K0: ws_src[f] = sum_e W_fe[f,e]*a_src[e]  (and dst) ------
__global__ void k0_ws(const float* __restrict__ Wfe,
                      const float* __restrict__ a_src,
                      const float* __restrict__ a_dst) {
    int t = threadIdx.x;  // 128 threads
    if (t < F_IN) {
        float s = 0.f;
        #pragma unroll 8
        for (int e = 0; e < E; e++) s += Wfe[t * E + e] * a_src[e];
        g_ws[t] = s;
    } else {
        int f = t - F_IN;
        float s = 0.f;
        #pragma unroll 8
        for (int e = 0; e < E; e++) s += Wfe[f * E + e] * a_dst[e];
        g_ws[F_IN + f] = s;
    }
}

// ---------------- K_wt: W^T fp16, padded [E][72] --------------------------
__global__ void k_wt(const float* __restrict__ Wfe) {
    int idx = blockIdx.x * 256 + threadIdx.x;   // 0..8191 = e*64+f
    int e = idx >> 6, f = idx & 63;
    g_wt[e * WT_STRIDE + f] = __float2half_rn(Wfe[f * E + e]);
}

// ---------------- K1a: normalize emb rows + emb-side attention dots --------
__global__ void k1a_norm(const float* __restrict__ emb,
                         const float* __restrict__ a_src,
                         const float* __restrict__ a_dst) {
    int n = blockIdx.x;
    int e = threadIdx.x;  // 128
    int lane = e & 31, wid = e >> 5;
    __shared__ float sm[12];
    float v  = emb[n * E + e];
    float r0 = v * v;
    float r1 = v * a_src[E + e];
    float r2 = v * a_dst[E + e];
    #pragma unroll
    for (int o = 16; o; o >>= 1) {
        r0 += __shfl_xor_sync(0xffffffffu, r0, o);
        r1 += __shfl_xor_sync(0xffffffffu, r1, o);
        r2 += __shfl_xor_sync(0xffffffffu, r2, o);
    }
    if (lane == 0) { sm[wid] = r0; sm[4 + wid] = r1; sm[8 + wid] = r2; }
    __syncthreads();
    float sumsq = sm[0] + sm[1] + sm[2] + sm[3];
    g_embn[n * E + e] = v * rsqrtf(sumsq);
    if (e == 0) {
        g_eemb_s[n] = sm[4] + sm[5] + sm[6] + sm[7];
        g_eemb_d[n] = sm[8] + sm[9] + sm[10] + sm[11];
    }
}

// ---------------- K1b-sim: tiled GEMM  sims = embn @ embn^T ---------------
#define KC 32
#define AS_STRIDE 33
__global__ void __launch_bounds__(256) k1b_sim() {
    __shared__ float As[64 * AS_STRIDE];
    __shared__ float Bs[64 * AS_STRIDE];
    int tid = threadIdx.x;
    int r0 = blockIdx.y * 64;
    int c0 = blockIdx.x * 64;
    int lrow = tid >> 5, lcol = tid & 31;
    int ty = tid >> 4, tx = tid & 15;

    float acc[4][4];
    #pragma unroll
    for (int i = 0; i < 4; i++)
        #pragma unroll
        for (int j = 0; j < 4; j++) acc[i][j] = 0.f;

    for (int kk = 0; kk < E; kk += KC) {
        #pragma unroll
        for (int it = 0; it < 8; it++) {
            int row = lrow + it * 8;
            As[row * AS_STRIDE + lcol] = g_embn[(size_t)(r0 + row) * E + kk + lcol];
            Bs[row * AS_STRIDE + lcol] = g_embn[(size_t)(c0 + row) * E + kk + lcol];
        }
        __syncthreads();

        #pragma unroll
        for (int k = 0; k < KC; k++) {
            float a[4], b[4];
            #pragma unroll
            for (int i = 0; i < 4; i++) a[i] = As[(ty * 4 + i) * AS_STRIDE + k];
            #pragma unroll
            for (int j = 0; j < 4; j++) b[j] = Bs[(tx * 4 + j) * AS_STRIDE + k];
            #pragma unroll
            for (int i = 0; i < 4; i++)
                #pragma unroll
                for (int j = 0; j < 4; j++) acc[i][j] += a[i] * b[j];
        }
        __syncthreads();
    }

    #pragma unroll
    for (int i = 0; i < 4; i++) {
        #pragma unroll
        for (int j = 0; j < 4; j++)
            g_sims[(size_t)(r0 + ty * 4 + i) * N + c0 + tx * 4 + j] = acc[i][j];
    }
}

// ---------------- K1b-sel: warp per row, top-32 (set semantics) ------------
__global__ void __launch_bounds__(256) k1b_sel() {
    int tid = threadIdx.x;
    int wid = tid >> 5, lane = tid & 31;
    int r = blockIdx.x * 8 + wid;

    const float* srow = g_sims + (size_t)r * N;
    float vals[32];
    #pragma unroll
    for (int j = 0; j < 32; j++) vals[j] = srow[j * 32 + lane];

    float bv = vals[0]; int bj = 0;
    #pragma unroll
    for (int j = 1; j < 32; j++)
        if (vals[j] > bv) { bv = vals[j]; bj = j; }

    for (int round = 0; round < TOPK; round++) {
        float wv = bv;
        int   wi = bj * 32 + lane;
        #pragma unroll
        for (int o = 16; o; o >>= 1) {
            float ov = __shfl_xor_sync(0xffffffffu, wv, o);
            int   oi = __shfl_xor_sync(0xffffffffu, wi, o);
            if (ov > wv || (ov == wv && oi < wi)) { wv = ov; wi = oi; }
        }
        if (lane == 0) g_idx[r * TOPK + round] = wi;
        if (lane == (wi & 31)) {
            int jw = wi >> 5;
            #pragma unroll
            for (int j = 0; j < 32; j++) if (j == jw) vals[j] = -INFINITY;
            bv = vals[0]; bj = 0;
            #pragma unroll
            for (int j = 1; j < 32; j++)
                if (vals[j] > bv) { bv = vals[j]; bj = j; }
        }
        __syncwarp();
    }
}

// ---------------- K2: h = x @ W_fe via tensor cores; fused e_s/e_d ---------
#define TOK 64
#define XS_STRIDE 72
#define CS_STRIDE 136

__device__ __forceinline__ void mma16816(float* c, const unsigned* a, const unsigned* b) {
    asm volatile(
        "mma.sync.aligned.m16n8k16.row.col.f32.f16.f16.f32 "
        "{%0,%1,%2,%3}, {%4,%5,%6,%7}, {%8,%9}, {%0,%1,%2,%3};\n"
        : "+f"(c[0]), "+f"(c[1]), "+f"(c[2]), "+f"(c[3])
        : "r"(a[0]), "r"(a[1]), "r"(a[2]), "r"(a[3]), "r"(b[0]), "r"(b[1]));
}

__global__ void __launch_bounds__(256) k2_tc(const float* __restrict__ x) {
    __shared__ __align__(16) char sbuf[TOK * XS_STRIDE * 2 + E * WT_STRIDE * 2];
    __half* xs = (__half*)sbuf;
    __half* Ws = (__half*)(sbuf + TOK * XS_STRIDE * 2);
    int tid = threadIdx.x;
    int t0 = blockIdx.x * TOK;

    {
        const uint4* wsrc = (const uint4*)g_wt;
        uint4* wdst = (uint4*)Ws;
        #pragma unroll
        for (int i = 0; i < 5; i++) {
            int idx = tid + i * 256;
            if (idx < (E * WT_STRIDE * 2) / 16) wdst[idx] = wsrc[idx];
        }
        const float4* xsrc = (const float4*)(x + (size_t)t0 * F_IN);
        const float4* ws4  = (const float4*)g_ws;
        int c4 = tid & 15;
        float4 wsv = __ldg(ws4 + c4);
        float4 wdv = __ldg(ws4 + 16 + c4);
        #pragma unroll
        for (int it = 0; it < 4; it++) {
            int idx = tid + it * 256;
            int row = idx >> 4;
            float4 v = xsrc[idx];
            __half2* dst = (__half2*)(xs + row * XS_STRIDE + c4 * 4);
            dst[0] = __floats2half2_rn(v.x, v.y);
            dst[1] = __floats2half2_rn(v.z, v.w);
            float s = v.x * wsv.x + v.y * wsv.y + v.z * wsv.z + v.w * wsv.w;
            float d = v.x * wdv.x + v.y * wdv.y + v.z * wdv.z + v.w * wdv.w;
            #pragma unroll
            for (int o = 8; o; o >>= 1) {
                s += __shfl_xor_sync(0xffffffffu, s, o);
                d += __shfl_xor_sync(0xffffffffu, d, o);
            }
            if (c4 == 0) {
                int gt = t0 + row;
                int n = gt & (N - 1);
                g_es[gt] = s + __ldg(&g_eemb_s[n]);
                g_ed[gt] = d + __ldg(&g_eemb_d[n]);
            }
        }
    }
    __syncthreads();

    int lane = tid & 31, warp = tid >> 5;
    int wm = warp & 3, wn = warp >> 2;
    int gid = lane >> 2, qid = lane & 3;

    float c[8][4];
    #pragma unroll
    for (int ni = 0; ni < 8; ni++)
        #pragma unroll
        for (int q = 0; q < 4; q++) c[ni][q] = 0.f;

    #pragma unroll
    for (int kk = 0; kk < F_IN; kk += 16) {
        unsigned a[4];
        {
            int r = wm * 16 + gid;
            int cb = qid * 2 + kk;
            a[0] = *(unsigned*)(xs + r * XS_STRIDE + cb);
            a[1] = *(unsigned*)(xs + (r + 8) * XS_STRIDE + cb);
            a[2] = *(unsigned*)(xs + r * XS_STRIDE + cb + 8);
            a[3] = *(unsigned*)(xs + (r + 8) * XS_STRIDE + cb + 8);
        }
        #pragma unroll
        for (int ni = 0; ni < 8; ni++) {
            int col = wn * 64 + ni * 8 + gid;
            int rb = qid * 2 + kk;
            unsigned bb[2];
            bb[0] = *(unsigned*)(Ws + col * WT_STRIDE + rb);
            bb[1] = *(unsigned*)(Ws + col * WT_STRIDE + rb + 8);
            mma16816(c[ni], a, bb);
        }
    }
    __syncthreads();

    __half* cs = (__half*)sbuf;
    #pragma unroll
    for (int ni = 0; ni < 8; ni++) {
        int r = wm * 16 + gid;
        int e = wn * 64 + ni * 8 + qid * 2;
        *(__half2*)(cs + r * CS_STRIDE + e) =
            __floats2half2_rn(c[ni][0], c[ni][1]);
        *(__half2*)(cs + (r + 8) * CS_STRIDE + e) =
            __floats2half2_rn(c[ni][2], c[ni][3]);
    }
    __syncthreads();

    uint4* dst = (uint4*)(g_h + (size_t)t0 * E);
    #pragma unroll
    for (int it = 0; it < 4; it++) {
        int idx = tid + it * 256;
        int row = idx >> 4;
        int c8  = idx & 15;
        dst[idx] = *(uint4*)(cs + row * CS_STRIDE + c8 * 8);
    }
}

// ---------------- K3: smem-resident SpMM attention ------------------------
// block = (batch, e-half); 1024 thr; h-half slab (128 KB) staged in smem.
// quarter-warp (8 lanes) per token, lane covers 8 e (one uint4 LDS per k).
__global__ void __launch_bounds__(1024) k3_spmm(const float* __restrict__ lin_W) {
    extern __shared__ __half hs[];     // [1024 rows][64 halves] = 128 KB
    int bx = blockIdx.x;
    int b  = bx >> 1;
    int h0 = (bx & 1) << 6;            // e offset: 0 or 64
    int tid = threadIdx.x;

    {   // stage the half-slab: 8192 uint4, coalesced 128B per row
        const uint4* src = (const uint4*)(g_h + (((size_t)b) << 10) * E);
        uint4* dst = (uint4*)hs;
        int cbase = h0 >> 3;           // 0 or 8 (uint4 offset within row)
        #pragma unroll
        for (int i = 0; i < 8; i++) {
            int idx = tid + (i << 10);
            int n = idx >> 3, c = idx & 7;
            dst[idx] = src[(n << 4) + cbase + c];
        }
    }
    __syncthreads();

    int lane = tid & 31, wid = tid >> 5;
    int g = lane >> 3, l8 = lane & 7;  // group 0..3 (token), lane-in-group

    // lin_W slice for this lane's 8 e's
    float lw[8];
    {
        const float4* lw4 = (const float4*)lin_W;
        float4 a0 = lw4[(h0 >> 2) + l8 * 2];
        float4 a1 = lw4[(h0 >> 2) + l8 * 2 + 1];
        lw[0] = a0.x; lw[1] = a0.y; lw[2] = a0.z; lw[3] = a0.w;
        lw[4] = a1.x; lw[5] = a1.y; lw[6] = a1.z; lw[7] = a1.w;
    }

    for (int pass = 0; pass < 8; pass++) {
        int n = (wid << 5) + (pass << 2) + g;
        int t = (b << 10) + n;

        // lane holds k = l8, l8+8, l8+16, l8+24
        float sc[4]; int ii[4];
        float es = g_es[t];
        float m = -1e30f;
        #pragma unroll
        for (int j = 0; j < 4; j++) {
            int k = l8 + (j << 3);
            int i = g_idx[(n << 5) + k];
            float v = es + g_ed[(b << 10) + i];
            v = v >= 0.f ? v : NEG_SLOPE * v;
            sc[j] = v; ii[j] = i;
            m = fmaxf(m, v);
        }
        #pragma unroll
        for (int o = 4; o; o >>= 1) m = fmaxf(m, __shfl_xor_sync(0xffffffffu, m, o));

        float s = 0.f;
        unsigned pk[4];
        #pragma unroll
        for (int j = 0; j < 4; j++) {
            float pe = __expf(sc[j] - m);
            unsigned pt = __float_as_uint(pe) & 0xFFFFFC00u;  // clear 10 low mantissa bits
            s += __uint_as_float(pt);
            pk[j] = pt | (unsigned)ii[j];                     // idx in low 10 bits
        }
        #pragma unroll
        for (int o = 4; o; o >>= 1) s += __shfl_xor_sync(0xffffffffu, s, o);

        float acc[8];
        #pragma unroll
        for (int q = 0; q < 8; q++) acc[q] = 0.f;
        #pragma unroll
        for (int k = 0; k < 32; k++) {
            unsigned w = __shfl_sync(0xffffffffu, pk[k >> 3], (lane & 24) + (k & 7));
            int   ridx = (int)(w & 0x3FFu);
            float a    = __uint_as_float(w & 0xFFFFFC00u);
            uint4 hv = ((const uint4*)hs)[(ridx << 3) + l8];
            const __half2* hp = (const __half2*)&hv;
            #pragma unroll
            for (int q = 0; q < 4; q++) {
                float2 f = __half22float2(hp[q]);
                acc[q * 2]     += a * f.x;
                acc[q * 2 + 1] += a * f.y;
            }
        }
        // relu(acc/s)·lw = (relu(acc)·lw)/s  since s > 0
        float part = 0.f;
        #pragma unroll
        for (int q = 0; q < 8; q++) part += fmaxf(acc[q], 0.f) * lw[q];
        part *= (1.f / s);
        #pragma unroll
        for (int o = 4; o; o >>= 1) part += __shfl_xor_sync(0xffffffffu, part, o);
        if (l8 == 0) g_part[((bx & 1) << 16) + t] = part;
    }
}

// ---------------- K_comb: combine e-half partials + bias -------------------
__global__ void k_comb(const float* __restrict__ lin_b, float* __restrict__ y) {
    int t = blockIdx.x * 256 + threadIdx.x;
    y[t] = g_part[t] + g_part[(B * N) + t] + lin_b[0];
}

// ---------------- launch (single stream, fully serial) ---------------------
extern "C" void kernel_launch(void* const* d_in, const int* in_sizes, int n_in,
                              void* d_out, int out_size) {
    const float* x     = (const float*)d_in[0];
    const float* emb   = (const float*)d_in[1];
    const float* Wfe   = (const float*)d_in[2];
    const float* a_src = (const float*)d_in[3];
    const float* a_dst = (const float*)d_in[4];
    const float* lin_W = (const float*)d_in[5];
    const float* lin_b = (const float*)d_in[6];
    float* y = (float*)d_out;

    static bool attr_set = false;
    if (!attr_set) {
        cudaFuncSetAttribute(k3_spmm, cudaFuncAttributeMaxDynamicSharedMemorySize,
                             131072);
        attr_set = true;
    }

    k0_ws<<<1, 128>>>(Wfe, a_src, a_dst);
    k_wt<<<(E * F_IN) / 256, 256>>>(Wfe);
    k1a_norm<<<N, 128>>>(emb, a_src, a_dst);
    {
        dim3 gsim(N / 64, N / 64);
        k1b_sim<<<gsim, 256>>>();
    }
    k1b_sel<<<N / 8, 256>>>();
    k2_tc<<<(B * N) / TOK, 256>>>(x);
    k3_spmm<<<2 * B, 1024, 131072>>>(lin_W);
    k_comb<<<(B * N) / 256, 256>>>(lin_b, y);
}

// round 12
// speedup vs baseline: 1.6595x; 1.0046x over previous
#include <cuda_runtime.h>
#include <cuda_fp16.h>
#include <math.h>

#define B 64
#define N 1024
#define F_IN 64
#define E 128
#define TOPK 32
#define NEG_SLOPE 0.2f

// ---------------- scratch (device globals; no allocation allowed) ----------
__device__ __align__(16) __half g_h[B * N * E];    // 16 MB, fp16 storage
__device__ float g_es[B * N];
__device__ float g_ed[B * N];
__device__ __align__(16) float g_embn[N * E];      // normalized emb
__device__ float g_eemb_s[N];
__device__ float g_eemb_d[N];
__device__ __align__(16) float g_ws[2 * F_IN];     // [ws_src | ws_dst]
__device__ int   g_idx[N * TOPK];
__device__ __align__(16) float g_sims[N * N];      // 4 MB cosine sims
__device__ float g_part[2 * B * N];                // per-e-half partial dots
#define WT_STRIDE 72
__device__ __align__(16) __half g_wt[E * WT_STRIDE];  // W^T fp16, padded rows

// ---------------- K_pre: fused k0_ws + k_wt + k1a_norm --------------------
// grid = 1024 (norm rows) + 1 (ws) + 64 (wt) = 1089 blocks x 128 threads.
__global__ void k_pre(const float* __restrict__ emb,
                      const float* __restrict__ Wfe,
                      const float* __restrict__ a_src,
                      const float* __restrict__ a_dst) {
    int bid = blockIdx.x;
    int t = threadIdx.x;  // 128

    if (bid < N) {
        // ---- k1a: normalize emb row + emb-side attention dots ----
        int n = bid;
        int lane = t & 31, wid = t >> 5;
        __shared__ float sm[12];
        float v  = emb[n * E + t];
        float r0 = v * v;
        float r1 = v * a_src[E + t];
        float r2 = v * a_dst[E + t];
        #pragma unroll
        for (int o = 16; o; o >>= 1) {
            r0 += __shfl_xor_sync(0xffffffffu, r0, o);
            r1 += __shfl_xor_sync(0xffffffffu, r1, o);
            r2 += __shfl_xor_sync(0xffffffffu, r2, o);
        }
        if (lane == 0) { sm[wid] = r0; sm[4 + wid] = r1; sm[8 + wid] = r2; }
        __syncthreads();
        float sumsq = sm[0] + sm[1] + sm[2] + sm[3];
        g_embn[n * E + t] = v * rsqrtf(sumsq);
        if (t == 0) {
            g_eemb_s[n] = sm[4] + sm[5] + sm[6] + sm[7];
            g_eemb_d[n] = sm[8] + sm[9] + sm[10] + sm[11];
        }
    } else if (bid == N) {
        // ---- k0: ws vectors ----
        if (t < F_IN) {
            float s = 0.f;
            #pragma unroll 8
            for (int e = 0; e < E; e++) s += Wfe[t * E + e] * a_src[e];
            g_ws[t] = s;
        } else {
            int f = t - F_IN;
            float s = 0.f;
            #pragma unroll 8
            for (int e = 0; e < E; e++) s += Wfe[f * E + e] * a_dst[e];
            g_ws[F_IN + f] = s;
        }
    } else {
        // ---- k_wt: W^T fp16, padded [E][72] ----
        int idx = (bid - N - 1) * 128 + t;   // 0..8191 = e*64+f
        int e = idx >> 6, f = idx & 63;
        g_wt[e * WT_STRIDE + f] = __float2half_rn(Wfe[f * E + e]);
    }
}

// ---------------- K1b-sim: tiled GEMM, k-major smem (float4 loads) ---------
#define KC 32
__global__ void __launch_bounds__(256) k1b_sim() {
    __shared__ float As[KC][68];   // [k][row], 68 pad: 16B-aligned rows
    __shared__ float Bs[KC][68];
    int tid = threadIdx.x;
    int r0 = blockIdx.y * 64;
    int c0 = blockIdx.x * 64;
    int lrow = tid >> 5, lcol = tid & 31;   // load: warp = one 128B row chunk
    int ty = tid >> 4, tx = tid & 15;       // compute: 4x4 per thread

    float acc[4][4];
    #pragma unroll
    for (int i = 0; i < 4; i++)
        #pragma unroll
        for (int j = 0; j < 4; j++) acc[i][j] = 0.f;

    for (int kk = 0; kk < E; kk += KC) {
        #pragma unroll
        for (int it = 0; it < 8; it++) {
            int row = lrow + it * 8;
            As[lcol][row] = g_embn[(size_t)(r0 + row) * E + kk + lcol];
            Bs[lcol][row] = g_embn[(size_t)(c0 + row) * E + kk + lcol];
        }
        __syncthreads();

        #pragma unroll
        for (int k = 0; k < KC; k++) {
            float4 av = *(const float4*)&As[k][ty * 4];
            float4 bv = *(const float4*)&Bs[k][tx * 4];
            float a[4] = {av.x, av.y, av.z, av.w};
            float b[4] = {bv.x, bv.y, bv.z, bv.w};
            #pragma unroll
            for (int i = 0; i < 4; i++)
                #pragma unroll
                for (int j = 0; j < 4; j++) acc[i][j] += a[i] * b[j];
        }
        __syncthreads();
    }

    #pragma unroll
    for (int i = 0; i < 4; i++) {
        #pragma unroll
        for (int j = 0; j < 4; j++)
            g_sims[(size_t)(r0 + ty * 4 + i) * N + c0 + tx * 4 + j] = acc[i][j];
    }
}

// ---------------- K1b-sel: warp per row, top-32 (set semantics) ------------
__global__ void __launch_bounds__(256) k1b_sel() {
    int tid = threadIdx.x;
    int wid = tid >> 5, lane = tid & 31;
    int r = blockIdx.x * 8 + wid;

    const float* srow = g_sims + (size_t)r * N;
    float vals[32];
    #pragma unroll
    for (int j = 0; j < 32; j++) vals[j] = srow[j * 32 + lane];

    float bv = vals[0]; int bj = 0;
    #pragma unroll
    for (int j = 1; j < 32; j++)
        if (vals[j] > bv) { bv = vals[j]; bj = j; }

    for (int round = 0; round < TOPK; round++) {
        float wv = bv;
        int   wi = bj * 32 + lane;
        #pragma unroll
        for (int o = 16; o; o >>= 1) {
            float ov = __shfl_xor_sync(0xffffffffu, wv, o);
            int   oi = __shfl_xor_sync(0xffffffffu, wi, o);
            if (ov > wv || (ov == wv && oi < wi)) { wv = ov; wi = oi; }
        }
        if (lane == 0) g_idx[r * TOPK + round] = wi;
        if (lane == (wi & 31)) {
            int jw = wi >> 5;
            #pragma unroll
            for (int j = 0; j < 32; j++) if (j == jw) vals[j] = -INFINITY;
            bv = vals[0]; bj = 0;
            #pragma unroll
            for (int j = 1; j < 32; j++)
                if (vals[j] > bv) { bv = vals[j]; bj = j; }
        }
        __syncwarp();
    }
}

// ---------------- K2: h = x @ W_fe via tensor cores; fused e_s/e_d ---------
#define TOK 64
#define XS_STRIDE 72
#define CS_STRIDE 136

__device__ __forceinline__ void mma16816(float* c, const unsigned* a, const unsigned* b) {
    asm volatile(
        "mma.sync.aligned.m16n8k16.row.col.f32.f16.f16.f32 "
        "{%0,%1,%2,%3}, {%4,%5,%6,%7}, {%8,%9}, {%0,%1,%2,%3};\n"
        : "+f"(c[0]), "+f"(c[1]), "+f"(c[2]), "+f"(c[3])
        : "r"(a[0]), "r"(a[1]), "r"(a[2]), "r"(a[3]), "r"(b[0]), "r"(b[1]));
}

__global__ void __launch_bounds__(256) k2_tc(const float* __restrict__ x) {
    __shared__ __align__(16) char sbuf[TOK * XS_STRIDE * 2 + E * WT_STRIDE * 2];
    __half* xs = (__half*)sbuf;
    __half* Ws = (__half*)(sbuf + TOK * XS_STRIDE * 2);
    int tid = threadIdx.x;
    int t0 = blockIdx.x * TOK;

    {
        const uint4* wsrc = (const uint4*)g_wt;
        uint4* wdst = (uint4*)Ws;
        #pragma unroll
        for (int i = 0; i < 5; i++) {
            int idx = tid + i * 256;
            if (idx < (E * WT_STRIDE * 2) / 16) wdst[idx] = wsrc[idx];
        }
        const float4* xsrc = (const float4*)(x + (size_t)t0 * F_IN);
        const float4* ws4  = (const float4*)g_ws;
        int c4 = tid & 15;
        float4 wsv = __ldg(ws4 + c4);
        float4 wdv = __ldg(ws4 + 16 + c4);
        #pragma unroll
        for (int it = 0; it < 4; it++) {
            int idx = tid + it * 256;
            int row = idx >> 4;
            float4 v = xsrc[idx];
            __half2* dst = (__half2*)(xs + row * XS_STRIDE + c4 * 4);
            dst[0] = __floats2half2_rn(v.x, v.y);
            dst[1] = __floats2half2_rn(v.z, v.w);
            float s = v.x * wsv.x + v.y * wsv.y + v.z * wsv.z + v.w * wsv.w;
            float d = v.x * wdv.x + v.y * wdv.y + v.z * wdv.z + v.w * wdv.w;
            #pragma unroll
            for (int o = 8; o; o >>= 1) {
                s += __shfl_xor_sync(0xffffffffu, s, o);
                d += __shfl_xor_sync(0xffffffffu, d, o);
            }
            if (c4 == 0) {
                int gt = t0 + row;
                int n = gt & (N - 1);
                g_es[gt] = s + __ldg(&g_eemb_s[n]);
                g_ed[gt] = d + __ldg(&g_eemb_d[n]);
            }
        }
    }
    __syncthreads();

    int lane = tid & 31, warp = tid >> 5;
    int wm = warp & 3, wn = warp >> 2;
    int gid = lane >> 2, qid = lane & 3;

    float c[8][4];
    #pragma unroll
    for (int ni = 0; ni < 8; ni++)
        #pragma unroll
        for (int q = 0; q < 4; q++) c[ni][q] = 0.f;

    #pragma unroll
    for (int kk = 0; kk < F_IN; kk += 16) {
        unsigned a[4];
        {
            int r = wm * 16 + gid;
            int cb = qid * 2 + kk;
            a[0] = *(unsigned*)(xs + r * XS_STRIDE + cb);
            a[1] = *(unsigned*)(xs + (r + 8) * XS_STRIDE + cb);
            a[2] = *(unsigned*)(xs + r * XS_STRIDE + cb + 8);
            a[3] = *(unsigned*)(xs + (r + 8) * XS_STRIDE + cb + 8);
        }
        #pragma unroll
        for (int ni = 0; ni < 8; ni++) {
            int col = wn * 64 + ni * 8 + gid;
            int rb = qid * 2 + kk;
            unsigned bb[2];
            bb[0] = *(unsigned*)(Ws + col * WT_STRIDE + rb);
            bb[1] = *(unsigned*)(Ws + col * WT_STRIDE + rb + 8);
            mma16816(c[ni], a, bb);
        }
    }
    __syncthreads();

    __half* cs = (__half*)sbuf;
    #pragma unroll
    for (int ni = 0; ni < 8; ni++) {
        int r = wm * 16 + gid;
        int e = wn * 64 + ni * 8 + qid * 2;
        *(__half2*)(cs + r * CS_STRIDE + e) =
            __floats2half2_rn(c[ni][0], c[ni][1]);
        *(__half2*)(cs + (r + 8) * CS_STRIDE + e) =
            __floats2half2_rn(c[ni][2], c[ni][3]);
    }
    __syncthreads();

    uint4* dst = (uint4*)(g_h + (size_t)t0 * E);
    #pragma unroll
    for (int it = 0; it < 4; it++) {
        int idx = tid + it * 256;
        int row = idx >> 4;
        int c8  = idx & 15;
        dst[idx] = *(uint4*)(cs + row * CS_STRIDE + c8 * 8);
    }
}

// ---------------- K3: smem-resident SpMM attention ------------------------
__global__ void __launch_bounds__(1024) k3_spmm(const float* __restrict__ lin_W) {
    extern __shared__ __half hs[];     // [1024 rows][64 halves] = 128 KB
    int bx = blockIdx.x;
    int b  = bx >> 1;
    int h0 = (bx & 1) << 6;            // e offset: 0 or 64
    int tid = threadIdx.x;

    {   // stage the half-slab: 8192 uint4, coalesced
        const uint4* src = (const uint4*)(g_h + (((size_t)b) << 10) * E);
        uint4* dst = (uint4*)hs;
        int cbase = h0 >> 3;
        #pragma unroll
        for (int i = 0; i < 8; i++) {
            int idx = tid + (i << 10);
            int n = idx >> 3, c = idx & 7;
            dst[idx] = src[(n << 4) + cbase + c];
        }
    }
    __syncthreads();

    int lane = tid & 31, wid = tid >> 5;
    int g = lane >> 3, l8 = lane & 7;

    float lw[8];
    {
        const float4* lw4 = (const float4*)lin_W;
        float4 a0 = lw4[(h0 >> 2) + l8 * 2];
        float4 a1 = lw4[(h0 >> 2) + l8 * 2 + 1];
        lw[0] = a0.x; lw[1] = a0.y; lw[2] = a0.z; lw[3] = a0.w;
        lw[4] = a1.x; lw[5] = a1.y; lw[6] = a1.z; lw[7] = a1.w;
    }

    for (int pass = 0; pass < 8; pass++) {
        int n = (wid << 5) + (pass << 2) + g;
        int t = (b << 10) + n;

        float sc[4]; int ii[4];
        float es = g_es[t];
        float m = -1e30f;
        #pragma unroll
        for (int j = 0; j < 4; j++) {
            int k = l8 + (j << 3);
            int i = g_idx[(n << 5) + k];
            float v = es + g_ed[(b << 10) + i];
            v = v >= 0.f ? v : NEG_SLOPE * v;
            sc[j] = v; ii[j] = i;
            m = fmaxf(m, v);
        }
        #pragma unroll
        for (int o = 4; o; o >>= 1) m = fmaxf(m, __shfl_xor_sync(0xffffffffu, m, o));

        float s = 0.f;
        unsigned pk[4];
        #pragma unroll
        for (int j = 0; j < 4; j++) {
            float pe = __expf(sc[j] - m);
            unsigned pt = __float_as_uint(pe) & 0xFFFFFC00u;
            s += __uint_as_float(pt);
            pk[j] = pt | (unsigned)ii[j];
        }
        #pragma unroll
        for (int o = 4; o; o >>= 1) s += __shfl_xor_sync(0xffffffffu, s, o);

        float acc[8];
        #pragma unroll
        for (int q = 0; q < 8; q++) acc[q] = 0.f;
        #pragma unroll
        for (int k = 0; k < 32; k++) {
            unsigned w = __shfl_sync(0xffffffffu, pk[k >> 3], (lane & 24) + (k & 7));
            int   ridx = (int)(w & 0x3FFu);
            float a    = __uint_as_float(w & 0xFFFFFC00u);
            uint4 hv = ((const uint4*)hs)[(ridx << 3) + l8];
            const __half2* hp = (const __half2*)&hv;
            #pragma unroll
            for (int q = 0; q < 4; q++) {
                float2 f = __half22float2(hp[q]);
                acc[q * 2]     += a * f.x;
                acc[q * 2 + 1] += a * f.y;
            }
        }
        float part = 0.f;
        #pragma unroll
        for (int q = 0; q < 8; q++) part += fmaxf(acc[q], 0.f) * lw[q];
        part *= (1.f / s);
        #pragma unroll
        for (int o = 4; o; o >>= 1) part += __shfl_xor_sync(0xffffffffu, part, o);
        if (l8 == 0) g_part[((bx & 1) << 16) + t] = part;
    }
}

// ---------------- K_comb: combine e-half partials + bias -------------------
__global__ void k_comb(const float* __restrict__ lin_b, float* __restrict__ y) {
    int t = blockIdx.x * 256 + threadIdx.x;
    y[t] = g_part[t] + g_part[(B * N) + t] + lin_b[0];
}

// ---------------- launch (single stream, fully serial, 6 kernels) ----------
extern "C" void kernel_launch(void* const* d_in, const int* in_sizes, int n_in,
                              void* d_out, int out_size) {
    const float* x     = (const float*)d_in[0];
    const float* emb   = (const float*)d_in[1];
    const float* Wfe   = (const float*)d_in[2];
    const float* a_src = (const float*)d_in[3];
    const float* a_dst = (const float*)d_in[4];
    const float* lin_W = (const float*)d_in[5];
    const float* lin_b = (const float*)d_in[6];
    float* y = (float*)d_out;

    static bool attr_set = false;
    if (!attr_set) {
        cudaFuncSetAttribute(k3_spmm, cudaFuncAttributeMaxDynamicSharedMemorySize,
                             131072);
        attr_set = true;
    }

    k_pre<<<N + 1 + 64, 128>>>(emb, Wfe, a_src, a_dst);
    {
        dim3 gsim(N / 64, N / 64);
        k1b_sim<<<gsim, 256>>>();
    }
    k1b_sel<<<N / 8, 256>>>();
    k2_tc<<<(B * N) / TOK, 256>>>(x);
    k3_spmm<<<2 * B, 1024, 131072>>>(lin_W);
    k_comb<<<(B * N) / 256, 256>>>(lin_b, y);
}